// round 16
// baseline (speedup 1.0000x reference)
#include <cuda_runtime.h>
#include <cuda_bf16.h>
#include <cstdint>
#include <cstddef>

#define NB 8
#define NL 4096
#define ND 1024
#define NROWS (NB*NL)   // 32768

// ---- scratch (device globals; no allocation allowed) ----
__device__ float    g_Q[(size_t)NROWS * ND];
__device__ float    g_K[(size_t)NROWS * ND];
__device__ float    g_V[(size_t)NROWS * ND];      // becomes U (=T@Vb) in place
__device__ float    g_O[(size_t)NROWS * ND];
__device__ float    g_A[(size_t)NB * 64 * 64 * 64];
// bf16 2-plane fragment-ordered operands for the scan
__device__ uint32_t g_Qfh [(size_t)NROWS * ND / 2];
__device__ uint32_t g_Qfm [(size_t)NROWS * ND / 2];
__device__ uint32_t g_Wfh [(size_t)NROWS * ND / 2];   // -W
__device__ uint32_t g_Wfm [(size_t)NROWS * ND / 2];
__device__ uint32_t g_Ktfh[(size_t)NROWS * ND / 2];   // K (B-frag order, j-packed)
__device__ uint32_t g_Ktfm[(size_t)NROWS * ND / 2];

__device__ __forceinline__ uint32_t f2tf32(float x) {
    uint32_t r;
    asm("cvt.rna.tf32.f32 %0, %1;" : "=r"(r) : "f"(x));
    return r;
}
__device__ __forceinline__ unsigned short bf16bits(float x) {
    return __bfloat16_as_ushort(__float2bfloat16(x));
}
__device__ __forceinline__ float bf16f(unsigned short u) {
    return __uint_as_float(((uint32_t)u) << 16);
}
__device__ __forceinline__ void packsplit(float a, float b, uint32_t& h, uint32_t& m) {
    unsigned short h0 = bf16bits(a), h1 = bf16bits(b);
    unsigned short m0 = bf16bits(a - bf16f(h0)), m1 = bf16bits(b - bf16f(h1));
    h = (uint32_t)h0 | ((uint32_t)h1 << 16);
    m = (uint32_t)m0 | ((uint32_t)m1 << 16);
}

#define MMA_TF32(d, a, b0, b1) \
    asm volatile("mma.sync.aligned.m16n8k8.row.col.f32.tf32.tf32.f32 " \
        "{%0,%1,%2,%3}, {%4,%5,%6,%7}, {%8,%9}, {%0,%1,%2,%3};" \
        : "+f"((d)[0]), "+f"((d)[1]), "+f"((d)[2]), "+f"((d)[3]) \
        : "r"((a)[0]), "r"((a)[1]), "r"((a)[2]), "r"((a)[3]), "r"(b0), "r"(b1))

#define MMA_BF16(d, a, b0, b1) \
    asm volatile("mma.sync.aligned.m16n8k16.row.col.f32.bf16.bf16.f32 " \
        "{%0,%1,%2,%3}, {%4,%5,%6,%7}, {%8,%9}, {%0,%1,%2,%3};" \
        : "+f"((d)[0]), "+f"((d)[1]), "+f"((d)[2]), "+f"((d)[3]) \
        : "r"((a)[0]), "r"((a)[1]), "r"((a)[2]), "r"((a)[3]), "r"(b0), "r"(b1))

// =====================================================================
// tf32 mma.sync GEMM: C(MxN) = A(MxK) @ W(NxK)^T + bias(N)
// If gridDim.x == 3*(N/128): fused mode, blockIdx.x%3 selects matrix.
// =====================================================================
#define GPITCH 20
#define GASZ   (128 * GPITCH)
#define GSMEM  (4 * GASZ * 4)   // 40960 bytes

__global__ void __launch_bounds__(256, 2) gemm_mma(
    const float* __restrict__ A,
    const float* __restrict__ W0, const float* __restrict__ W1, const float* __restrict__ W2,
    const float* __restrict__ b0p, const float* __restrict__ b1p, const float* __restrict__ b2p,
    float* __restrict__ C0, float* __restrict__ C1, float* __restrict__ C2,
    int M, int N, int K)
{
    extern __shared__ uint32_t smg[];
    const int t    = threadIdx.x;
    const int wid  = t >> 5;
    const int lane = t & 31;
    const int wm   = wid & 1;
    const int wn   = wid >> 1;
    const int m0   = blockIdx.y * 128;

    int mat, n0;
    if ((int)gridDim.x == (N / 128)) { mat = 0; n0 = blockIdx.x * 128; }
    else { mat = blockIdx.x % 3; n0 = (blockIdx.x / 3) * 128; }
    const float* Wm   = (mat == 0) ? W0 : (mat == 1) ? W1 : W2;
    const float* bias = (mat == 0) ? b0p : (mat == 1) ? b1p : b2p;
    float*       C    = (mat == 0) ? C0 : (mat == 1) ? C1 : C2;

    const int lr = lane >> 2;
    const int lc = lane & 3;

    const float* Ap = A  + (size_t)m0 * K;
    const float* Bp = Wm + (size_t)n0 * K;

    float acc[4][4][4];
#pragma unroll
    for (int i = 0; i < 4; i++)
#pragma unroll
        for (int j = 0; j < 4; j++)
#pragma unroll
            for (int x = 0; x < 4; x++) acc[i][j][x] = 0.f;

#pragma unroll
    for (int i = 0; i < 2; i++) {
        int idx = t + i * 256;
        int r = idx >> 2, c4 = idx & 3;
        float4 va = *(const float4*)(Ap + (size_t)r * K + c4 * 4);
        uint32_t* dst = &smg[r * GPITCH + c4 * 4];
        dst[0] = f2tf32(va.x); dst[1] = f2tf32(va.y);
        dst[2] = f2tf32(va.z); dst[3] = f2tf32(va.w);
        float4 vb = *(const float4*)(Bp + (size_t)r * K + c4 * 4);
        uint32_t* dstb = &smg[GASZ + r * GPITCH + c4 * 4];
        dstb[0] = f2tf32(vb.x); dstb[1] = f2tf32(vb.y);
        dstb[2] = f2tf32(vb.z); dstb[3] = f2tf32(vb.w);
    }
    __syncthreads();

    const int nkt = K >> 4;   // 64
    for (int kt = 0; kt < nkt; kt++) {
        const int cur = kt & 1;
        float4 ra[2], rb[2];
        if (kt + 1 < nkt) {
            const int ko = (kt + 1) * 16;
#pragma unroll
            for (int i = 0; i < 2; i++) {
                int idx = t + i * 256;
                int r = idx >> 2, c4 = idx & 3;
                ra[i] = *(const float4*)(Ap + (size_t)r * K + ko + c4 * 4);
                rb[i] = *(const float4*)(Bp + (size_t)r * K + ko + c4 * 4);
            }
        }
        const uint32_t* As = smg + cur * 2 * GASZ;
        const uint32_t* Bs = As + GASZ;
#pragma unroll
        for (int k8 = 0; k8 < 2; k8++) {
            const int kb = k8 * 8 + lc;
            uint32_t af[4][4], bf[4][2];
#pragma unroll
            for (int mt = 0; mt < 4; mt++) {
                int r = wm * 64 + mt * 16 + lr;
                af[mt][0] = As[r * GPITCH + kb];
                af[mt][1] = As[(r + 8) * GPITCH + kb];
                af[mt][2] = As[r * GPITCH + kb + 4];
                af[mt][3] = As[(r + 8) * GPITCH + kb + 4];
            }
#pragma unroll
            for (int nt = 0; nt < 4; nt++) {
                int n = wn * 32 + nt * 8 + lr;
                bf[nt][0] = Bs[n * GPITCH + kb];
                bf[nt][1] = Bs[n * GPITCH + kb + 4];
            }
#pragma unroll
            for (int mt = 0; mt < 4; mt++)
#pragma unroll
                for (int nt = 0; nt < 4; nt++)
                    MMA_TF32(acc[mt][nt], af[mt], bf[nt][0], bf[nt][1]);
        }
        if (kt + 1 < nkt) {
            uint32_t* dA = smg + (1 - cur) * 2 * GASZ;
            uint32_t* dB = dA + GASZ;
#pragma unroll
            for (int i = 0; i < 2; i++) {
                int idx = t + i * 256;
                int r = idx >> 2, c4 = idx & 3;
                uint32_t* da = &dA[r * GPITCH + c4 * 4];
                da[0] = f2tf32(ra[i].x); da[1] = f2tf32(ra[i].y);
                da[2] = f2tf32(ra[i].z); da[3] = f2tf32(ra[i].w);
                uint32_t* db = &dB[r * GPITCH + c4 * 4];
                db[0] = f2tf32(rb[i].x); db[1] = f2tf32(rb[i].y);
                db[2] = f2tf32(rb[i].z); db[3] = f2tf32(rb[i].w);
            }
        }
        __syncthreads();
    }

#pragma unroll
    for (int mt = 0; mt < 4; mt++) {
        int r = m0 + wm * 64 + mt * 16 + lr;
#pragma unroll
        for (int nt = 0; nt < 4; nt++) {
            int c = n0 + wn * 32 + nt * 8 + 2 * lc;
            float2 bv = *(const float2*)&bias[c];
            float2 o0, o1;
            o0.x = acc[mt][nt][0] + bv.x; o0.y = acc[mt][nt][1] + bv.y;
            o1.x = acc[mt][nt][2] + bv.x; o1.y = acc[mt][nt][3] + bv.y;
            *(float2*)&C[(size_t)r * N + c]       = o0;
            *(float2*)&C[(size_t)(r + 8) * N + c] = o1;
        }
    }
}

// =====================================================================
// prep (tensor, ping-pong buffers, blocked fsub) — R13 proven-fastest
// =====================================================================
#define PPAD 36
#define TP   36
#define P_SA0  0
#define P_SB0  (64 * PPAD)
#define P_SA1  (2 * 64 * PPAD)
#define P_SB1  (3 * 64 * PPAD)
#define P_TS   (4 * 64 * PPAD)
#define P_THI  (P_TS + 4096)
#define P_TMID (P_THI + 64 * TP)
#define P_BETA (P_TMID + 64 * TP)
#define PREP_SMEM ((P_BETA + 64) * 4)    // 71936 bytes

__global__ void __launch_bounds__(256, 2) prep_kernel()
{
    extern __shared__ float smp[];
    float* T_s    = smp + P_TS;
    uint32_t* Thi = (uint32_t*)(smp + P_THI);
    uint32_t* Tmid= (uint32_t*)(smp + P_TMID);
    float* beta_s = smp + P_BETA;

    const int t  = threadIdx.x;
    const int bc = blockIdx.x;
    const size_t row0 = (size_t)(bc >> 6) * NL + (size_t)(bc & 63) * 64;
    const size_t fb   = (size_t)bc * 32768;

    const int lkk = t & 31, ljr = t >> 5;
    const int lane = t & 31, lr = lane >> 2, lc = lane & 3;
    const int grp  = t >> 5;

    const int  wmt   = grp & 3;
    const bool isAQ  = (grp >= 4);
    const int  ntmax = 2 * wmt + 2;

    float acc[8][4];
#pragma unroll
    for (int nt = 0; nt < 8; nt++)
#pragma unroll
        for (int x = 0; x < 4; x++) acc[nt][x] = 0.f;

    float* sAc = smp + P_SA0;
    float* sBc = smp + P_SB0;
    float* sAn = smp + P_SA1;
    float* sBn = smp + P_SB1;

#pragma unroll
    for (int h = 0; h < 8; h++) {
        int j = ljr + h * 8;
        sAc[j * PPAD + lkk] = g_K[(row0 + j) * ND + lkk];
        sBc[j * PPAD + lkk] = g_Q[(row0 + j) * ND + lkk];
    }
    __syncthreads();

    for (int kt = 0; kt < 32; kt++) {
        const int k0 = kt * 32;
        float pk[8], pq[8];
        if (kt < 31) {
#pragma unroll
            for (int h = 0; h < 8; h++) {
                int j = ljr + h * 8;
                pk[h] = g_K[(row0 + j) * ND + k0 + 32 + lkk];
                pq[h] = g_Q[(row0 + j) * ND + k0 + 32 + lkk];
            }
        }

        {
            int k16l = grp >> 2, mg = grp & 3;
            int r0 = mg * 16 + lr;
            int kb = k16l * 16 + 2 * lc;
            uint32_t ah[4], am[4];
            packsplit(sBc[r0 * PPAD + kb],           sBc[r0 * PPAD + kb + 1],           ah[0], am[0]);
            packsplit(sBc[(r0 + 8) * PPAD + kb],     sBc[(r0 + 8) * PPAD + kb + 1],     ah[1], am[1]);
            packsplit(sBc[r0 * PPAD + kb + 8],       sBc[r0 * PPAD + kb + 9],           ah[2], am[2]);
            packsplit(sBc[(r0 + 8) * PPAD + kb + 8], sBc[(r0 + 8) * PPAD + kb + 9],     ah[3], am[3]);
            size_t o = fb + (size_t)(((k0 >> 4) + k16l) * 4 + mg) * 128 + lane * 4;
            *(uint4*)&g_Qfh[o] = make_uint4(ah[0], ah[1], ah[2], ah[3]);
            *(uint4*)&g_Qfm[o] = make_uint4(am[0], am[1], am[2], am[3]);
        }
#pragma unroll
        for (int h = 0; h < 2; h++) {
            int g2 = grp + h * 8;
            int ngl = g2 & 3, j16 = g2 >> 2;
            int nn = ngl * 8 + lr;
            int jb = j16 * 16 + 2 * lc;
            uint32_t bh0, bm0, bh1, bm1;
            packsplit(sAc[jb * PPAD + nn],       sAc[(jb + 1) * PPAD + nn], bh0, bm0);
            packsplit(sAc[(jb + 8) * PPAD + nn], sAc[(jb + 9) * PPAD + nn], bh1, bm1);
            size_t o = fb + (size_t)(((k0 >> 3) + ngl) * 4 + j16) * 64 + lane * 2;
            *(uint2*)&g_Ktfh[o] = make_uint2(bh0, bh1);
            *(uint2*)&g_Ktfm[o] = make_uint2(bm0, bm1);
        }

        const float* Am = isAQ ? sBc : sAc;
#pragma unroll
        for (int k16l = 0; k16l < 2; k16l++) {
            const int kk = k16l * 16 + 2 * lc;
            float2 a0 = *(const float2*)&Am[(wmt * 16 + lr) * PPAD + kk];
            float2 a1 = *(const float2*)&Am[(wmt * 16 + lr + 8) * PPAD + kk];
            float2 a2 = *(const float2*)&Am[(wmt * 16 + lr) * PPAD + kk + 8];
            float2 a3 = *(const float2*)&Am[(wmt * 16 + lr + 8) * PPAD + kk + 8];
            uint32_t ah[4], am[4];
            packsplit(a0.x, a0.y, ah[0], am[0]);
            packsplit(a1.x, a1.y, ah[1], am[1]);
            packsplit(a2.x, a2.y, ah[2], am[2]);
            packsplit(a3.x, a3.y, ah[3], am[3]);
#pragma unroll
            for (int nt = 0; nt < 8; nt++) {
                if (nt >= ntmax) break;
                float2 b0 = *(const float2*)&sAc[(nt * 8 + lr) * PPAD + kk];
                float2 b1 = *(const float2*)&sAc[(nt * 8 + lr) * PPAD + kk + 8];
                uint32_t bh0, bm0, bh1, bm1;
                packsplit(b0.x, b0.y, bh0, bm0);
                packsplit(b1.x, b1.y, bh1, bm1);
                MMA_BF16(acc[nt], ah, bh0, bh1);
                MMA_BF16(acc[nt], ah, bm0, bm1);
                MMA_BF16(acc[nt], am, bh0, bh1);
            }
        }

        if (kt < 31) {
#pragma unroll
            for (int h = 0; h < 8; h++) {
                int j = ljr + h * 8;
                sAn[j * PPAD + lkk] = pk[h];
                sBn[j * PPAD + lkk] = pq[h];
            }
        }
        __syncthreads();
        float* tmp;
        tmp = sAc; sAc = sAn; sAn = tmp;
        tmp = sBc; sBc = sBn; sBn = tmp;
    }

    if (!isAQ) {
#pragma unroll
        for (int nt = 0; nt < 8; nt++) {
            if (nt >= ntmax) break;
#pragma unroll
            for (int x = 0; x < 4; x++) {
                int i = wmt * 16 + lr + ((x >> 1) << 3);
                int j = nt * 8 + 2 * lc + (x & 1);
                if (i == j) beta_s[i] = 1.f / (acc[nt][x] + 1e-6f);
            }
        }
    }
    __syncthreads();

    if (!isAQ) {
#pragma unroll
        for (int nt = 0; nt < 8; nt++)
#pragma unroll
            for (int x = 0; x < 4; x++) {
                int i = wmt * 16 + lr + ((x >> 1) << 3);
                int j = nt * 8 + 2 * lc + (x & 1);
                float v = (nt < ntmax && j < i) ? (-beta_s[i] * acc[nt][x]) : 0.f;
                T_s[i * 64 + j] = v;
            }
    } else {
        float* Aout = g_A + (size_t)bc * 4096;
#pragma unroll
        for (int nt = 0; nt < 8; nt++)
#pragma unroll
            for (int x = 0; x < 4; x++) {
                int i = wmt * 16 + lr + ((x >> 1) << 3);
                int j = nt * 8 + 2 * lc + (x & 1);
                Aout[i * 64 + j] = (nt < ntmax && j <= i) ? acc[nt][x] : 0.f;
            }
    }
    __syncthreads();

    for (int blk = 0; blk < 4; blk++) {
        if (grp == 0) {
            for (int ii = 0; ii < 16; ii++) {
                int i = blk * 16 + ii;
                float rt = (lane < 16) ? T_s[i * 64 + blk * 16 + lane] : 0.f;
                __syncwarp();
                float s0 = 0.f, s1 = 0.f;
                int c0 = lane, c1 = lane + 32;
                for (int j = blk * 16; j < i; j++) {
                    float coef = __shfl_sync(0xffffffffu, rt, j - blk * 16);
                    float t0 = (j > c0) ? T_s[j * 64 + c0] : 0.f;
                    float t1 = (j > c1) ? T_s[j * 64 + c1] : 0.f;
                    s0 += coef * t0;
                    s1 += coef * t1;
                }
                if (c0 < i) T_s[i * 64 + c0] += s0;
                if (c1 < i) T_s[i * 64 + c1] += s1;
                __syncwarp();
            }
        }
        __syncthreads();
        if (blk < 3) {
            const int C = 16 * (blk + 1);
            const int R = 64 - C;
            for (int idx = t; idx < R * C; idx += 256) {
                int i  = C + idx / C;
                int tc = idx % C;
                float s = 0.f;
#pragma unroll
                for (int jj = 0; jj < 16; jj++) {
                    int j = blk * 16 + jj;
                    float coef = T_s[i * 64 + j];
                    float v    = (j > tc) ? T_s[j * 64 + tc] : 0.f;
                    s += coef * v;
                }
                T_s[i * 64 + tc] += s;
            }
            __syncthreads();
        }
    }
    if (t < 64) T_s[t * 64 + t] += 1.f;
    __syncthreads();

#pragma unroll
    for (int h = 0; h < 8; h++) {
        int idx = t + h * 256;
        int rT = idx >> 5, jp = idx & 31;
        uint32_t hw, mw;
        packsplit(T_s[rT * 64 + 2 * jp], T_s[rT * 64 + 2 * jp + 1], hw, mw);
        Thi[rT * TP + jp]  = hw;
        Tmid[rT * TP + jp] = mw;
    }

    const int g2  = grp >> 2;
    const int mt2 = grp & 3;

#pragma unroll
    for (int h = 0; h < 8; h++) {
        int j = ljr + h * 8;
        float bj = beta_s[j];
        sAc[j * PPAD + lkk] = g_K[(row0 + j) * ND + lkk] * bj;
        sBc[j * PPAD + lkk] = g_V[(row0 + j) * ND + lkk] * bj;
    }
    __syncthreads();

    for (int dt = 0; dt < 32; dt++) {
        const int d0 = dt * 32;
        float pk[8], pv[8];
        if (dt < 31) {
#pragma unroll
            for (int h = 0; h < 8; h++) {
                int j = ljr + h * 8;
                pk[h] = g_K[(row0 + j) * ND + d0 + 32 + lkk];
                pv[h] = g_V[(row0 + j) * ND + d0 + 32 + lkk];
            }
        }

        float accW[2][4], accU[2][4];
#pragma unroll
        for (int ti = 0; ti < 2; ti++)
#pragma unroll
            for (int x = 0; x < 4; x++) { accW[ti][x] = 0.f; accU[ti][x] = 0.f; }

#pragma unroll
        for (int j16 = 0; j16 < 4; j16++) {
            const int jk = j16 * 16;
            int ar = (mt2 * 16 + lr) * TP + j16 * 8 + lc;
            uint32_t ah[4], am[4];
            ah[0] = Thi[ar];              am[0] = Tmid[ar];
            ah[1] = Thi[ar + 8 * TP];     am[1] = Tmid[ar + 8 * TP];
            ah[2] = Thi[ar + 4];          am[2] = Tmid[ar + 4];
            ah[3] = Thi[ar + 8 * TP + 4]; am[3] = Tmid[ar + 8 * TP + 4];
#pragma unroll
            for (int ti = 0; ti < 2; ti++) {
                const int dd = (2 * g2 + ti) * 8 + lr;
                {
                    uint32_t kh0, km0, kh1, km1;
                    packsplit(sAc[(jk + 2 * lc) * PPAD + dd],
                              sAc[(jk + 2 * lc + 1) * PPAD + dd], kh0, km0);
                    packsplit(sAc[(jk + 2 * lc + 8) * PPAD + dd],
                              sAc[(jk + 2 * lc + 9) * PPAD + dd], kh1, km1);
                    MMA_BF16(accW[ti], ah, kh0, kh1);
                    MMA_BF16(accW[ti], ah, km0, km1);
                    MMA_BF16(accW[ti], am, kh0, kh1);
                }
                {
                    uint32_t vh0, vm0, vh1, vm1;
                    packsplit(sBc[(jk + 2 * lc) * PPAD + dd],
                              sBc[(jk + 2 * lc + 1) * PPAD + dd], vh0, vm0);
                    packsplit(sBc[(jk + 2 * lc + 8) * PPAD + dd],
                              sBc[(jk + 2 * lc + 9) * PPAD + dd], vh1, vm1);
                    MMA_BF16(accU[ti], ah, vh0, vh1);
                    MMA_BF16(accU[ti], ah, vm0, vm1);
                    MMA_BF16(accU[ti], am, vh0, vh1);
                }
            }
        }

#pragma unroll
        for (int ti = 0; ti < 2; ti++) {
            int dcol = d0 + (2 * g2 + ti) * 8 + 2 * lc;
            size_t rA = (row0 + mt2 * 16 + lr) * ND + dcol;
            *(float2*)&g_V[rA]          = make_float2(accU[ti][0], accU[ti][1]);
            *(float2*)&g_V[rA + 8 * ND] = make_float2(accU[ti][2], accU[ti][3]);
        }
        {
            uint32_t w0h, w0m, w1h, w1m, w2h, w2m, w3h, w3m;
            packsplit(-accW[0][0], -accW[0][1], w0h, w0m);
            packsplit(-accW[0][2], -accW[0][3], w1h, w1m);
            packsplit(-accW[1][0], -accW[1][1], w2h, w2m);
            packsplit(-accW[1][2], -accW[1][3], w3h, w3m);
            size_t o = fb + (size_t)(((d0 >> 4) + g2) * 4 + mt2) * 128 + lane * 4;
            *(uint4*)&g_Wfh[o] = make_uint4(w0h, w1h, w2h, w3h);
            *(uint4*)&g_Wfm[o] = make_uint4(w0m, w1m, w2m, w3m);
        }

        if (dt < 31) {
#pragma unroll
            for (int h = 0; h < 8; h++) {
                int j = ljr + h * 8;
                float bj = beta_s[j];
                sAn[j * PPAD + lkk] = pk[h] * bj;
                sBn[j * PPAD + lkk] = pv[h] * bj;
            }
        }
        __syncthreads();
        float* tmp;
        tmp = sAc; sAc = sAn; sAn = tmp;
        tmp = sBc; sBc = sBn; sBn = tmp;
    }
}

// =====================================================================
// scan (tensor, bf16x3, dual column-halves; S in MMA accumulator regs)
// grid (32 colblocks, 8 batches), 512 thr — proven form (R12/R15)
// =====================================================================
#define SP 516
#define UP 36
#define OFF_SM (32 * SP * 4)
#define OFF_UH (2 * 32 * SP * 4)
#define OFF_UM (OFF_UH + 32 * UP * 4)
#define SCAN_SMEM3 (OFF_UM + 32 * UP * 4)   // 141312

#define BARH() asm volatile("bar.sync %0, 256;" :: "r"(1 + half) : "memory")

__global__ void __launch_bounds__(512, 1) scan_tc()
{
    extern __shared__ char smc[];
    uint32_t* ShP = (uint32_t*)smc;
    uint32_t* SmP = (uint32_t*)(smc + OFF_SM);
    uint32_t* UhP = (uint32_t*)(smc + OFF_UH);
    uint32_t* UmP = (uint32_t*)(smc + OFF_UM);
    unsigned short* Uh16 = (unsigned short*)UhP;
    unsigned short* Um16 = (unsigned short*)UmP;

    const int t    = threadIdx.x;
    const int half = t >> 8;
    const int t2   = t & 255;
    const int lane = t & 31;
    const int wid2 = t2 >> 5;
    const int lr   = lane >> 2;
    const int lc   = lane & 3;
    const int b    = blockIdx.y;
    const int cb0  = blockIdx.x * 32 + half * 16;
    const int colb = half * 16;

    for (int i = t; i < 32 * SP; i += 512) { ShP[i] = 0u; SmP[i] = 0u; }
    __syncthreads();

    const int  mg  = wid2 & 3;
    const bool isQ = (wid2 >= 4);
    const int  dn  = wid2 * 128;

    float Sreg[16][4];
#pragma unroll
    for (int ng = 0; ng < 16; ng++)
#pragma unroll
        for (int x = 0; x < 4; x++) Sreg[ng][x] = 0.f;

    for (int n = 0; n < 64; n++) {
        const size_t row0  = (size_t)b * NL + (size_t)n * 64;
        const size_t cbase = (size_t)b * 64 + n;

        float acc[2][4];
        if (!isQ) {
            const size_t rr = row0 + mg * 16 + lr;
#pragma unroll
            for (int nt = 0; nt < 2; nt++) {
                int cc = cb0 + nt * 8 + 2 * lc;
                float2 v0 = *(const float2*)&g_V[rr * ND + cc];
                float2 v1 = *(const float2*)&g_V[(rr + 8) * ND + cc];
                acc[nt][0] = v0.x; acc[nt][1] = v0.y;
                acc[nt][2] = v1.x; acc[nt][3] = v1.y;
            }
        } else {
#pragma unroll
            for (int nt = 0; nt < 2; nt++)
#pragma unroll
                for (int x = 0; x < 4; x++) acc[nt][x] = 0.f;
        }
        {
            const uint32_t* Afh = (isQ ? g_Qfh : g_Wfh) + cbase * 32768;
            const uint32_t* Afm = (isQ ? g_Qfm : g_Wfm) + cbase * 32768;
#pragma unroll 2
            for (int k16 = 0; k16 < 64; k16++) {
                uint4 h4 = *(const uint4*)&Afh[(size_t)(k16 * 4 + mg) * 128 + lane * 4];
                uint4 m4 = *(const uint4*)&Afm[(size_t)(k16 * 4 + mg) * 128 + lane * 4];
                uint32_t ah[4] = {h4.x, h4.y, h4.z, h4.w};
                uint32_t am[4] = {m4.x, m4.y, m4.z, m4.w};
#pragma unroll
                for (int nt = 0; nt < 2; nt++) {
                    int base = (colb + nt * 8 + lr) * SP + k16 * 8 + lc;
                    uint32_t bh0 = ShP[base], bh1 = ShP[base + 4];
                    uint32_t bm0 = SmP[base], bm1 = SmP[base + 4];
                    MMA_BF16(acc[nt], ah, bh0, bh1);
                    MMA_BF16(acc[nt], ah, bm0, bm1);
                    MMA_BF16(acc[nt], am, bh0, bh1);
                }
            }
        }
        if (!isQ) {
#pragma unroll
            for (int nt = 0; nt < 2; nt++) {
#pragma unroll
                for (int x = 0; x < 4; x++) {
                    int cc = colb + nt * 8 + 2 * lc + (x & 1);
                    int j  = mg * 16 + lr + ((x >> 1) << 3);
                    float v = acc[nt][x];
                    unsigned short h = bf16bits(v);
                    Uh16[cc * 72 + j] = h;
                    Um16[cc * 72 + j] = bf16bits(v - bf16f(h));
                }
            }
        }
        BARH();

        if (isQ) {
            const float* Ab = g_A + cbase * 4096;
#pragma unroll
            for (int j16 = 0; j16 < 4; j16++) {
                const float* ar0 = &Ab[(mg * 16 + lr) * 64 + j16 * 16 + 2 * lc];
                const float* ar1 = ar0 + 8 * 64;
                float2 p0 = *(const float2*)ar0;
                float2 p1 = *(const float2*)ar1;
                float2 p2 = *(const float2*)(ar0 + 8);
                float2 p3 = *(const float2*)(ar1 + 8);
                uint32_t ah[4], am[4];
                packsplit(p0.x, p0.y, ah[0], am[0]);
                packsplit(p1.x, p1.y, ah[1], am[1]);
                packsplit(p2.x, p2.y, ah[2], am[2]);
                packsplit(p3.x, p3.y, ah[3], am[3]);
#pragma unroll
                for (int nt = 0; nt < 2; nt++) {
                    int base = (colb + nt * 8 + lr) * UP + j16 * 8 + lc;
                    uint32_t bh0 = UhP[base], bh1 = UhP[base + 4];
                    uint32_t bm0 = UmP[base], bm1 = UmP[base + 4];
                    MMA_BF16(acc[nt], ah, bh0, bh1);
                    MMA_BF16(acc[nt], ah, bm0, bm1);
                    MMA_BF16(acc[nt], am, bh0, bh1);
                }
            }
            const size_t rr = row0 + mg * 16 + lr;
#pragma unroll
            for (int nt = 0; nt < 2; nt++) {
                int cc = cb0 + nt * 8 + 2 * lc;
                *(float2*)&g_O[rr * ND + cc]       = make_float2(acc[nt][0], acc[nt][1]);
                *(float2*)&g_O[(rr + 8) * ND + cc] = make_float2(acc[nt][2], acc[nt][3]);
            }
        }

        {
            const uint32_t* Kfh = g_Ktfh + cbase * 32768;
            const uint32_t* Kfm = g_Ktfm + cbase * 32768;
            const int ng0 = dn >> 3;
#pragma unroll
            for (int j16 = 0; j16 < 4; j16++) {
                int b0 = (colb + lr) * UP + j16 * 8 + lc;
                int b1 = (colb + lr + 8) * UP + j16 * 8 + lc;
                uint32_t ah[4] = {UhP[b0], UhP[b1], UhP[b0 + 4], UhP[b1 + 4]};
                uint32_t am[4] = {UmP[b0], UmP[b1], UmP[b0 + 4], UmP[b1 + 4]};
#pragma unroll
                for (int ng = 0; ng < 16; ng++) {
                    size_t fo = (size_t)((ng0 + ng) * 4 + j16) * 64 + lane * 2;
                    uint2 kh = *(const uint2*)&Kfh[fo];
                    uint2 km = *(const uint2*)&Kfm[fo];
                    MMA_BF16(Sreg[ng], ah, kh.x, kh.y);
                    MMA_BF16(Sreg[ng], ah, km.x, km.y);
                    MMA_BF16(Sreg[ng], am, kh.x, kh.y);
                }
            }
#pragma unroll
            for (int ng = 0; ng < 16; ng++) {
#pragma unroll
                for (int h8 = 0; h8 < 2; h8++) {
                    int cc = colb + lr + h8 * 8;
                    int widx = cc * SP + (dn >> 1) + ng * 4 + lc;
                    uint32_t hw, mw;
                    packsplit(Sreg[ng][h8 * 2], Sreg[ng][h8 * 2 + 1], hw, mw);
                    ShP[widx] = hw;
                    SmP[widx] = mw;
                }
            }
        }
        BARH();
    }
}

// =====================================================================
extern "C" void kernel_launch(void* const* d_in, const int* in_sizes, int n_in,
                              void* d_out, int out_size)
{
    int base = 1;
    if (n_in >= 10 && in_sizes[1] == 1) base = 2;
    const float* X    = (const float*)d_in[0];
    const float* Wq_w = (const float*)d_in[base + 0];
    const float* Wq_b = (const float*)d_in[base + 1];
    const float* Wk_w = (const float*)d_in[base + 2];
    const float* Wk_b = (const float*)d_in[base + 3];
    const float* Wv_w = (const float*)d_in[base + 4];
    const float* Wv_b = (const float*)d_in[base + 5];
    const float* Wo_w = (const float*)d_in[base + 6];
    const float* Wo_b = (const float*)d_in[base + 7];
    float* out = (float*)d_out;

    float *pQ, *pK, *pV, *pO;
    cudaGetSymbolAddress((void**)&pQ, g_Q);
    cudaGetSymbolAddress((void**)&pK, g_K);
    cudaGetSymbolAddress((void**)&pV, g_V);
    cudaGetSymbolAddress((void**)&pO, g_O);

    cudaFuncSetAttribute(gemm_mma, cudaFuncAttributeMaxDynamicSharedMemorySize, GSMEM);
    // fused QKV: grid.x = 3 * N/128, blockIdx.x%3 selects matrix
    gemm_mma<<<dim3(3 * ND / 128, NROWS / 128), 256, GSMEM>>>(
        X, Wq_w, Wk_w, Wv_w, Wq_b, Wk_b, Wv_b, pQ, pK, pV, NROWS, ND, ND);
    cudaFuncSetAttribute(prep_kernel, cudaFuncAttributeMaxDynamicSharedMemorySize, PREP_SMEM);
    prep_kernel<<<NB * 64, 256, PREP_SMEM>>>();
    cudaFuncSetAttribute(scan_tc, cudaFuncAttributeMaxDynamicSharedMemorySize, SCAN_SMEM3);
    scan_tc<<<dim3(32, NB), 512, SCAN_SMEM3>>>();
    // O-GEMM: non-fused mode (grid.x == N/128)
    gemm_mma<<<dim3(ND / 128, NROWS / 128), 256, GSMEM>>>(
        pO, Wo_w, Wo_w, Wo_w, Wo_b, Wo_b, Wo_b, out, out, out, NROWS, ND, ND);
}

// round 17
// speedup vs baseline: 1.0301x; 1.0301x over previous
#include <cuda_runtime.h>
#include <cuda_bf16.h>
#include <cstdint>
#include <cstddef>

#define NB 8
#define NL 4096
#define ND 1024
#define NROWS (NB*NL)   // 32768

// ---- scratch (device globals; no allocation allowed) ----
__device__ float    g_Q[(size_t)NROWS * ND];
__device__ float    g_K[(size_t)NROWS * ND];
__device__ float    g_V[(size_t)NROWS * ND];      // becomes U (=T@Vb) in place
__device__ float    g_O[(size_t)NROWS * ND];
__device__ float    g_A[(size_t)NB * 64 * 64 * 64];
__device__ uint32_t g_Xt[(size_t)NROWS * ND];     // X (then O) as tf32 bits
__device__ uint32_t g_Wq4[(size_t)ND * ND];
__device__ uint32_t g_Wk4[(size_t)ND * ND];
__device__ uint32_t g_Wv4[(size_t)ND * ND];
__device__ uint32_t g_Wo4[(size_t)ND * ND];
// bf16 2-plane fragment-ordered operands for the scan
__device__ uint32_t g_Qfh [(size_t)NROWS * ND / 2];
__device__ uint32_t g_Qfm [(size_t)NROWS * ND / 2];
__device__ uint32_t g_Wfh [(size_t)NROWS * ND / 2];   // -W
__device__ uint32_t g_Wfm [(size_t)NROWS * ND / 2];
__device__ uint32_t g_Ktfh[(size_t)NROWS * ND / 2];   // K (B-frag order, j-packed)
__device__ uint32_t g_Ktfm[(size_t)NROWS * ND / 2];

__device__ __forceinline__ uint32_t f2tf32(float x) {
    uint32_t r;
    asm("cvt.rna.tf32.f32 %0, %1;" : "=r"(r) : "f"(x));
    return r;
}
__device__ __forceinline__ unsigned short bf16bits(float x) {
    return __bfloat16_as_ushort(__float2bfloat16(x));
}
__device__ __forceinline__ float bf16f(unsigned short u) {
    return __uint_as_float(((uint32_t)u) << 16);
}
__device__ __forceinline__ void packsplit(float a, float b, uint32_t& h, uint32_t& m) {
    unsigned short h0 = bf16bits(a), h1 = bf16bits(b);
    unsigned short m0 = bf16bits(a - bf16f(h0)), m1 = bf16bits(b - bf16f(h1));
    h = (uint32_t)h0 | ((uint32_t)h1 << 16);
    m = (uint32_t)m0 | ((uint32_t)m1 << 16);
}
__device__ __forceinline__ uint32_t smem_u32(const void* p) {
    uint32_t a;
    asm("{ .reg .u64 t; cvta.to.shared.u64 t, %1; cvt.u32.u64 %0, t; }" : "=r"(a) : "l"(p));
    return a;
}

#define MMA_TF32(d, a, b0, b1) \
    asm volatile("mma.sync.aligned.m16n8k8.row.col.f32.tf32.tf32.f32 " \
        "{%0,%1,%2,%3}, {%4,%5,%6,%7}, {%8,%9}, {%0,%1,%2,%3};" \
        : "+f"((d)[0]), "+f"((d)[1]), "+f"((d)[2]), "+f"((d)[3]) \
        : "r"((a)[0]), "r"((a)[1]), "r"((a)[2]), "r"((a)[3]), "r"(b0), "r"(b1))

#define MMA_BF16(d, a, b0, b1) \
    asm volatile("mma.sync.aligned.m16n8k16.row.col.f32.bf16.bf16.f32 " \
        "{%0,%1,%2,%3}, {%4,%5,%6,%7}, {%8,%9}, {%0,%1,%2,%3};" \
        : "+f"((d)[0]), "+f"((d)[1]), "+f"((d)[2]), "+f"((d)[3]) \
        : "r"((a)[0]), "r"((a)[1]), "r"((a)[2]), "r"((a)[3]), "r"(b0), "r"(b1))

#define CP_ASYNC16(saddr, gptr) \
    asm volatile("cp.async.ca.shared.global [%0], [%1], 16;" :: "r"(saddr), "l"(gptr))
#define CP_COMMIT() asm volatile("cp.async.commit_group;")
#define CP_WAIT2()  asm volatile("cp.async.wait_group 2;")

// =====================================================================
// elementwise fp32 -> tf32-bits conversion (float4 granular)
// =====================================================================
__global__ void __launch_bounds__(256) conv_tf32(
    const float* __restrict__ in, uint32_t* __restrict__ outp, int n4)
{
    int i = blockIdx.x * 256 + threadIdx.x;
    if (i < n4) {
        float4 v = ((const float4*)in)[i];
        ((uint4*)outp)[i] = make_uint4(f2tf32(v.x), f2tf32(v.y), f2tf32(v.z), f2tf32(v.w));
    }
}

// =====================================================================
// tf32 GEMM on pre-converted inputs, 4-stage cp.async pipeline
// C(MxN) = A(MxK) @ W(NxK)^T + bias(N); A,W are tf32 bits.
// =====================================================================
#define GPITCH 20
#define GSTAGE (128 * GPITCH)          // uint32 per array per stage
#define GSMEM  (4 * 2 * GSTAGE * 4)    // 81920 bytes

__global__ void __launch_bounds__(256, 2) gemm_tf32(
    const uint32_t* __restrict__ A, const uint32_t* __restrict__ Wm,
    const float* __restrict__ bias, float* __restrict__ C,
    int M, int N, int K)
{
    extern __shared__ uint32_t smg[];
    const uint32_t sbase = smem_u32(smg);
    const int t    = threadIdx.x;
    const int wid  = t >> 5;
    const int lane = t & 31;
    const int wm   = wid & 1;
    const int wn   = wid >> 1;
    const int m0   = blockIdx.y * 128;
    const int n0   = blockIdx.x * 128;
    const int lr   = lane >> 2;
    const int lc   = lane & 3;

    const uint32_t* Ap = A  + (size_t)m0 * K;
    const uint32_t* Bp = Wm + (size_t)n0 * K;

    // per-thread load coords (2 x 16B per array per stage)
    const int r0_ = (t + 0)   >> 2, c0_ = (t & 3) * 4;
    const int r1_ = (t + 256) >> 2, c1_ = c0_;

    float acc[4][4][4];
#pragma unroll
    for (int i = 0; i < 4; i++)
#pragma unroll
        for (int j = 0; j < 4; j++)
#pragma unroll
            for (int x = 0; x < 4; x++) acc[i][j][x] = 0.f;

    const int nkt = K >> 4;   // 64

    // prologue: stages 0..2
#pragma unroll
    for (int s = 0; s < 3; s++) {
        const int k0 = s * 16;
        uint32_t sa = sbase + (uint32_t)(s * 2 * GSTAGE) * 4;
        uint32_t sb = sa + (uint32_t)GSTAGE * 4;
        CP_ASYNC16(sa + (r0_ * GPITCH + c0_) * 4, Ap + (size_t)r0_ * K + k0 + c0_);
        CP_ASYNC16(sa + (r1_ * GPITCH + c1_) * 4, Ap + (size_t)r1_ * K + k0 + c1_);
        CP_ASYNC16(sb + (r0_ * GPITCH + c0_) * 4, Bp + (size_t)r0_ * K + k0 + c0_);
        CP_ASYNC16(sb + (r1_ * GPITCH + c1_) * 4, Bp + (size_t)r1_ * K + k0 + c1_);
        CP_COMMIT();
    }

    for (int kt = 0; kt < nkt; kt++) {
        CP_WAIT2();
        __syncthreads();

        const uint32_t* As = smg + (kt & 3) * 2 * GSTAGE;
        const uint32_t* Bs = As + GSTAGE;
#pragma unroll
        for (int k8 = 0; k8 < 2; k8++) {
            const int kb = k8 * 8 + lc;
            uint32_t af[4][4], bf[4][2];
#pragma unroll
            for (int mt = 0; mt < 4; mt++) {
                int r = wm * 64 + mt * 16 + lr;
                af[mt][0] = As[r * GPITCH + kb];
                af[mt][1] = As[(r + 8) * GPITCH + kb];
                af[mt][2] = As[r * GPITCH + kb + 4];
                af[mt][3] = As[(r + 8) * GPITCH + kb + 4];
            }
#pragma unroll
            for (int nt = 0; nt < 4; nt++) {
                int n = wn * 32 + nt * 8 + lr;
                bf[nt][0] = Bs[n * GPITCH + kb];
                bf[nt][1] = Bs[n * GPITCH + kb + 4];
            }
#pragma unroll
            for (int mt = 0; mt < 4; mt++)
#pragma unroll
                for (int nt = 0; nt < 4; nt++)
                    MMA_TF32(acc[mt][nt], af[mt], bf[nt][0], bf[nt][1]);
        }

        if (kt + 3 < nkt) {
            const int kn = (kt + 3) * 16;
            const int sn = (kt + 3) & 3;
            uint32_t sa = sbase + (uint32_t)(sn * 2 * GSTAGE) * 4;
            uint32_t sb = sa + (uint32_t)GSTAGE * 4;
            CP_ASYNC16(sa + (r0_ * GPITCH + c0_) * 4, Ap + (size_t)r0_ * K + kn + c0_);
            CP_ASYNC16(sa + (r1_ * GPITCH + c1_) * 4, Ap + (size_t)r1_ * K + kn + c1_);
            CP_ASYNC16(sb + (r0_ * GPITCH + c0_) * 4, Bp + (size_t)r0_ * K + kn + c0_);
            CP_ASYNC16(sb + (r1_ * GPITCH + c1_) * 4, Bp + (size_t)r1_ * K + kn + c1_);
        }
        CP_COMMIT();   // one group per iteration (possibly empty) keeps accounting exact
        __syncthreads();
    }

#pragma unroll
    for (int mt = 0; mt < 4; mt++) {
        int r = m0 + wm * 64 + mt * 16 + lr;
#pragma unroll
        for (int nt = 0; nt < 4; nt++) {
            int c = n0 + wn * 32 + nt * 8 + 2 * lc;
            float2 bv = *(const float2*)&bias[c];
            float2 o0, o1;
            o0.x = acc[mt][nt][0] + bv.x; o0.y = acc[mt][nt][1] + bv.y;
            o1.x = acc[mt][nt][2] + bv.x; o1.y = acc[mt][nt][3] + bv.y;
            *(float2*)&C[(size_t)r * N + c]       = o0;
            *(float2*)&C[(size_t)(r + 8) * N + c] = o1;
        }
    }
}

// =====================================================================
// prep (tensor, ping-pong buffers, blocked fsub) — R13 proven-fastest
// =====================================================================
#define PPAD 36
#define TP   36
#define P_SA0  0
#define P_SB0  (64 * PPAD)
#define P_SA1  (2 * 64 * PPAD)
#define P_SB1  (3 * 64 * PPAD)
#define P_TS   (4 * 64 * PPAD)
#define P_THI  (P_TS + 4096)
#define P_TMID (P_THI + 64 * TP)
#define P_BETA (P_TMID + 64 * TP)
#define PREP_SMEM ((P_BETA + 64) * 4)    // 71936 bytes

__global__ void __launch_bounds__(256, 2) prep_kernel()
{
    extern __shared__ float smp[];
    float* T_s    = smp + P_TS;
    uint32_t* Thi = (uint32_t*)(smp + P_THI);
    uint32_t* Tmid= (uint32_t*)(smp + P_TMID);
    float* beta_s = smp + P_BETA;

    const int t  = threadIdx.x;
    const int bc = blockIdx.x;
    const size_t row0 = (size_t)(bc >> 6) * NL + (size_t)(bc & 63) * 64;
    const size_t fb   = (size_t)bc * 32768;

    const int lkk = t & 31, ljr = t >> 5;
    const int lane = t & 31, lr = lane >> 2, lc = lane & 3;
    const int grp  = t >> 5;

    const int  wmt   = grp & 3;
    const bool isAQ  = (grp >= 4);
    const int  ntmax = 2 * wmt + 2;

    float acc[8][4];
#pragma unroll
    for (int nt = 0; nt < 8; nt++)
#pragma unroll
        for (int x = 0; x < 4; x++) acc[nt][x] = 0.f;

    float* sAc = smp + P_SA0;
    float* sBc = smp + P_SB0;
    float* sAn = smp + P_SA1;
    float* sBn = smp + P_SB1;

#pragma unroll
    for (int h = 0; h < 8; h++) {
        int j = ljr + h * 8;
        sAc[j * PPAD + lkk] = g_K[(row0 + j) * ND + lkk];
        sBc[j * PPAD + lkk] = g_Q[(row0 + j) * ND + lkk];
    }
    __syncthreads();

    for (int kt = 0; kt < 32; kt++) {
        const int k0 = kt * 32;
        float pk[8], pq[8];
        if (kt < 31) {
#pragma unroll
            for (int h = 0; h < 8; h++) {
                int j = ljr + h * 8;
                pk[h] = g_K[(row0 + j) * ND + k0 + 32 + lkk];
                pq[h] = g_Q[(row0 + j) * ND + k0 + 32 + lkk];
            }
        }

        {
            int k16l = grp >> 2, mg = grp & 3;
            int r0 = mg * 16 + lr;
            int kb = k16l * 16 + 2 * lc;
            uint32_t ah[4], am[4];
            packsplit(sBc[r0 * PPAD + kb],           sBc[r0 * PPAD + kb + 1],           ah[0], am[0]);
            packsplit(sBc[(r0 + 8) * PPAD + kb],     sBc[(r0 + 8) * PPAD + kb + 1],     ah[1], am[1]);
            packsplit(sBc[r0 * PPAD + kb + 8],       sBc[r0 * PPAD + kb + 9],           ah[2], am[2]);
            packsplit(sBc[(r0 + 8) * PPAD + kb + 8], sBc[(r0 + 8) * PPAD + kb + 9],     ah[3], am[3]);
            size_t o = fb + (size_t)(((k0 >> 4) + k16l) * 4 + mg) * 128 + lane * 4;
            *(uint4*)&g_Qfh[o] = make_uint4(ah[0], ah[1], ah[2], ah[3]);
            *(uint4*)&g_Qfm[o] = make_uint4(am[0], am[1], am[2], am[3]);
        }
#pragma unroll
        for (int h = 0; h < 2; h++) {
            int g2 = grp + h * 8;
            int ngl = g2 & 3, j16 = g2 >> 2;
            int nn = ngl * 8 + lr;
            int jb = j16 * 16 + 2 * lc;
            uint32_t bh0, bm0, bh1, bm1;
            packsplit(sAc[jb * PPAD + nn],       sAc[(jb + 1) * PPAD + nn], bh0, bm0);
            packsplit(sAc[(jb + 8) * PPAD + nn], sAc[(jb + 9) * PPAD + nn], bh1, bm1);
            size_t o = fb + (size_t)(((k0 >> 3) + ngl) * 4 + j16) * 64 + lane * 2;
            *(uint2*)&g_Ktfh[o] = make_uint2(bh0, bh1);
            *(uint2*)&g_Ktfm[o] = make_uint2(bm0, bm1);
        }

        const float* Am = isAQ ? sBc : sAc;
#pragma unroll
        for (int k16l = 0; k16l < 2; k16l++) {
            const int kk = k16l * 16 + 2 * lc;
            float2 a0 = *(const float2*)&Am[(wmt * 16 + lr) * PPAD + kk];
            float2 a1 = *(const float2*)&Am[(wmt * 16 + lr + 8) * PPAD + kk];
            float2 a2 = *(const float2*)&Am[(wmt * 16 + lr) * PPAD + kk + 8];
            float2 a3 = *(const float2*)&Am[(wmt * 16 + lr + 8) * PPAD + kk + 8];
            uint32_t ah[4], am[4];
            packsplit(a0.x, a0.y, ah[0], am[0]);
            packsplit(a1.x, a1.y, ah[1], am[1]);
            packsplit(a2.x, a2.y, ah[2], am[2]);
            packsplit(a3.x, a3.y, ah[3], am[3]);
#pragma unroll
            for (int nt = 0; nt < 8; nt++) {
                if (nt >= ntmax) break;
                float2 b0 = *(const float2*)&sAc[(nt * 8 + lr) * PPAD + kk];
                float2 b1 = *(const float2*)&sAc[(nt * 8 + lr) * PPAD + kk + 8];
                uint32_t bh0, bm0, bh1, bm1;
                packsplit(b0.x, b0.y, bh0, bm0);
                packsplit(b1.x, b1.y, bh1, bm1);
                MMA_BF16(acc[nt], ah, bh0, bh1);
                MMA_BF16(acc[nt], ah, bm0, bm1);
                MMA_BF16(acc[nt], am, bh0, bh1);
            }
        }

        if (kt < 31) {
#pragma unroll
            for (int h = 0; h < 8; h++) {
                int j = ljr + h * 8;
                sAn[j * PPAD + lkk] = pk[h];
                sBn[j * PPAD + lkk] = pq[h];
            }
        }
        __syncthreads();
        float* tmp;
        tmp = sAc; sAc = sAn; sAn = tmp;
        tmp = sBc; sBc = sBn; sBn = tmp;
    }

    if (!isAQ) {
#pragma unroll
        for (int nt = 0; nt < 8; nt++) {
            if (nt >= ntmax) break;
#pragma unroll
            for (int x = 0; x < 4; x++) {
                int i = wmt * 16 + lr + ((x >> 1) << 3);
                int j = nt * 8 + 2 * lc + (x & 1);
                if (i == j) beta_s[i] = 1.f / (acc[nt][x] + 1e-6f);
            }
        }
    }
    __syncthreads();

    if (!isAQ) {
#pragma unroll
        for (int nt = 0; nt < 8; nt++)
#pragma unroll
            for (int x = 0; x < 4; x++) {
                int i = wmt * 16 + lr + ((x >> 1) << 3);
                int j = nt * 8 + 2 * lc + (x & 1);
                float v = (nt < ntmax && j < i) ? (-beta_s[i] * acc[nt][x]) : 0.f;
                T_s[i * 64 + j] = v;
            }
    } else {
        float* Aout = g_A + (size_t)bc * 4096;
#pragma unroll
        for (int nt = 0; nt < 8; nt++)
#pragma unroll
            for (int x = 0; x < 4; x++) {
                int i = wmt * 16 + lr + ((x >> 1) << 3);
                int j = nt * 8 + 2 * lc + (x & 1);
                Aout[i * 64 + j] = (nt < ntmax && j <= i) ? acc[nt][x] : 0.f;
            }
    }
    __syncthreads();

    for (int blk = 0; blk < 4; blk++) {
        if (grp == 0) {
            for (int ii = 0; ii < 16; ii++) {
                int i = blk * 16 + ii;
                float rt = (lane < 16) ? T_s[i * 64 + blk * 16 + lane] : 0.f;
                __syncwarp();
                float s0 = 0.f, s1 = 0.f;
                int c0 = lane, c1 = lane + 32;
                for (int j = blk * 16; j < i; j++) {
                    float coef = __shfl_sync(0xffffffffu, rt, j - blk * 16);
                    float t0 = (j > c0) ? T_s[j * 64 + c0] : 0.f;
                    float t1 = (j > c1) ? T_s[j * 64 + c1] : 0.f;
                    s0 += coef * t0;
                    s1 += coef * t1;
                }
                if (c0 < i) T_s[i * 64 + c0] += s0;
                if (c1 < i) T_s[i * 64 + c1] += s1;
                __syncwarp();
            }
        }
        __syncthreads();
        if (blk < 3) {
            const int C = 16 * (blk + 1);
            const int R = 64 - C;
            for (int idx = t; idx < R * C; idx += 256) {
                int i  = C + idx / C;
                int tc = idx % C;
                float s = 0.f;
#pragma unroll
                for (int jj = 0; jj < 16; jj++) {
                    int j = blk * 16 + jj;
                    float coef = T_s[i * 64 + j];
                    float v    = (j > tc) ? T_s[j * 64 + tc] : 0.f;
                    s += coef * v;
                }
                T_s[i * 64 + tc] += s;
            }
            __syncthreads();
        }
    }
    if (t < 64) T_s[t * 64 + t] += 1.f;
    __syncthreads();

#pragma unroll
    for (int h = 0; h < 8; h++) {
        int idx = t + h * 256;
        int rT = idx >> 5, jp = idx & 31;
        uint32_t hw, mw;
        packsplit(T_s[rT * 64 + 2 * jp], T_s[rT * 64 + 2 * jp + 1], hw, mw);
        Thi[rT * TP + jp]  = hw;
        Tmid[rT * TP + jp] = mw;
    }

    const int g2  = grp >> 2;
    const int mt2 = grp & 3;

#pragma unroll
    for (int h = 0; h < 8; h++) {
        int j = ljr + h * 8;
        float bj = beta_s[j];
        sAc[j * PPAD + lkk] = g_K[(row0 + j) * ND + lkk] * bj;
        sBc[j * PPAD + lkk] = g_V[(row0 + j) * ND + lkk] * bj;
    }
    __syncthreads();

    for (int dt = 0; dt < 32; dt++) {
        const int d0 = dt * 32;
        float pk[8], pv[8];
        if (dt < 31) {
#pragma unroll
            for (int h = 0; h < 8; h++) {
                int j = ljr + h * 8;
                pk[h] = g_K[(row0 + j) * ND + d0 + 32 + lkk];
                pv[h] = g_V[(row0 + j) * ND + d0 + 32 + lkk];
            }
        }

        float accW[2][4], accU[2][4];
#pragma unroll
        for (int ti = 0; ti < 2; ti++)
#pragma unroll
            for (int x = 0; x < 4; x++) { accW[ti][x] = 0.f; accU[ti][x] = 0.f; }

#pragma unroll
        for (int j16 = 0; j16 < 4; j16++) {
            const int jk = j16 * 16;
            int ar = (mt2 * 16 + lr) * TP + j16 * 8 + lc;
            uint32_t ah[4], am[4];
            ah[0] = Thi[ar];              am[0] = Tmid[ar];
            ah[1] = Thi[ar + 8 * TP];     am[1] = Tmid[ar + 8 * TP];
            ah[2] = Thi[ar + 4];          am[2] = Tmid[ar + 4];
            ah[3] = Thi[ar + 8 * TP + 4]; am[3] = Tmid[ar + 8 * TP + 4];
#pragma unroll
            for (int ti = 0; ti < 2; ti++) {
                const int dd = (2 * g2 + ti) * 8 + lr;
                {
                    uint32_t kh0, km0, kh1, km1;
                    packsplit(sAc[(jk + 2 * lc) * PPAD + dd],
                              sAc[(jk + 2 * lc + 1) * PPAD + dd], kh0, km0);
                    packsplit(sAc[(jk + 2 * lc + 8) * PPAD + dd],
                              sAc[(jk + 2 * lc + 9) * PPAD + dd], kh1, km1);
                    MMA_BF16(accW[ti], ah, kh0, kh1);
                    MMA_BF16(accW[ti], ah, km0, km1);
                    MMA_BF16(accW[ti], am, kh0, kh1);
                }
                {
                    uint32_t vh0, vm0, vh1, vm1;
                    packsplit(sBc[(jk + 2 * lc) * PPAD + dd],
                              sBc[(jk + 2 * lc + 1) * PPAD + dd], vh0, vm0);
                    packsplit(sBc[(jk + 2 * lc + 8) * PPAD + dd],
                              sBc[(jk + 2 * lc + 9) * PPAD + dd], vh1, vm1);
                    MMA_BF16(accU[ti], ah, vh0, vh1);
                    MMA_BF16(accU[ti], ah, vm0, vm1);
                    MMA_BF16(accU[ti], am, vh0, vh1);
                }
            }
        }

#pragma unroll
        for (int ti = 0; ti < 2; ti++) {
            int dcol = d0 + (2 * g2 + ti) * 8 + 2 * lc;
            size_t rA = (row0 + mt2 * 16 + lr) * ND + dcol;
            *(float2*)&g_V[rA]          = make_float2(accU[ti][0], accU[ti][1]);
            *(float2*)&g_V[rA + 8 * ND] = make_float2(accU[ti][2], accU[ti][3]);
        }
        {
            uint32_t w0h, w0m, w1h, w1m, w2h, w2m, w3h, w3m;
            packsplit(-accW[0][0], -accW[0][1], w0h, w0m);
            packsplit(-accW[0][2], -accW[0][3], w1h, w1m);
            packsplit(-accW[1][0], -accW[1][1], w2h, w2m);
            packsplit(-accW[1][2], -accW[1][3], w3h, w3m);
            size_t o = fb + (size_t)(((d0 >> 4) + g2) * 4 + mt2) * 128 + lane * 4;
            *(uint4*)&g_Wfh[o] = make_uint4(w0h, w1h, w2h, w3h);
            *(uint4*)&g_Wfm[o] = make_uint4(w0m, w1m, w2m, w3m);
        }

        if (dt < 31) {
#pragma unroll
            for (int h = 0; h < 8; h++) {
                int j = ljr + h * 8;
                float bj = beta_s[j];
                sAn[j * PPAD + lkk] = pk[h] * bj;
                sBn[j * PPAD + lkk] = pv[h] * bj;
            }
        }
        __syncthreads();
        float* tmp;
        tmp = sAc; sAc = sAn; sAn = tmp;
        tmp = sBc; sBc = sBn; sBn = tmp;
    }
}

// =====================================================================
// scan (tensor, bf16x3, dual column-halves; S in MMA accumulator regs)
// grid (32 colblocks, 8 batches), 512 thr — proven form (R12)
// =====================================================================
#define SP 516
#define UP 36
#define OFF_SM (32 * SP * 4)
#define OFF_UH (2 * 32 * SP * 4)
#define OFF_UM (OFF_UH + 32 * UP * 4)
#define SCAN_SMEM3 (OFF_UM + 32 * UP * 4)   // 141312

#define BARH() asm volatile("bar.sync %0, 256;" :: "r"(1 + half) : "memory")

__global__ void __launch_bounds__(512, 1) scan_tc()
{
    extern __shared__ char smc[];
    uint32_t* ShP = (uint32_t*)smc;
    uint32_t* SmP = (uint32_t*)(smc + OFF_SM);
    uint32_t* UhP = (uint32_t*)(smc + OFF_UH);
    uint32_t* UmP = (uint32_t*)(smc + OFF_UM);
    unsigned short* Uh16 = (unsigned short*)UhP;
    unsigned short* Um16 = (unsigned short*)UmP;

    const int t    = threadIdx.x;
    const int half = t >> 8;
    const int t2   = t & 255;
    const int lane = t & 31;
    const int wid2 = t2 >> 5;
    const int lr   = lane >> 2;
    const int lc   = lane & 3;
    const int b    = blockIdx.y;
    const int cb0  = blockIdx.x * 32 + half * 16;
    const int colb = half * 16;

    for (int i = t; i < 32 * SP; i += 512) { ShP[i] = 0u; SmP[i] = 0u; }
    __syncthreads();

    const int  mg  = wid2 & 3;
    const bool isQ = (wid2 >= 4);
    const int  dn  = wid2 * 128;

    float Sreg[16][4];
#pragma unroll
    for (int ng = 0; ng < 16; ng++)
#pragma unroll
        for (int x = 0; x < 4; x++) Sreg[ng][x] = 0.f;

    for (int n = 0; n < 64; n++) {
        const size_t row0  = (size_t)b * NL + (size_t)n * 64;
        const size_t cbase = (size_t)b * 64 + n;

        float acc[2][4];
        if (!isQ) {
            const size_t rr = row0 + mg * 16 + lr;
#pragma unroll
            for (int nt = 0; nt < 2; nt++) {
                int cc = cb0 + nt * 8 + 2 * lc;
                float2 v0 = *(const float2*)&g_V[rr * ND + cc];
                float2 v1 = *(const float2*)&g_V[(rr + 8) * ND + cc];
                acc[nt][0] = v0.x; acc[nt][1] = v0.y;
                acc[nt][2] = v1.x; acc[nt][3] = v1.y;
            }
        } else {
#pragma unroll
            for (int nt = 0; nt < 2; nt++)
#pragma unroll
                for (int x = 0; x < 4; x++) acc[nt][x] = 0.f;
        }
        {
            const uint32_t* Afh = (isQ ? g_Qfh : g_Wfh) + cbase * 32768;
            const uint32_t* Afm = (isQ ? g_Qfm : g_Wfm) + cbase * 32768;
#pragma unroll 2
            for (int k16 = 0; k16 < 64; k16++) {
                uint4 h4 = *(const uint4*)&Afh[(size_t)(k16 * 4 + mg) * 128 + lane * 4];
                uint4 m4 = *(const uint4*)&Afm[(size_t)(k16 * 4 + mg) * 128 + lane * 4];
                uint32_t ah[4] = {h4.x, h4.y, h4.z, h4.w};
                uint32_t am[4] = {m4.x, m4.y, m4.z, m4.w};
#pragma unroll
                for (int nt = 0; nt < 2; nt++) {
                    int base = (colb + nt * 8 + lr) * SP + k16 * 8 + lc;
                    uint32_t bh0 = ShP[base], bh1 = ShP[base + 4];
                    uint32_t bm0 = SmP[base], bm1 = SmP[base + 4];
                    MMA_BF16(acc[nt], ah, bh0, bh1);
                    MMA_BF16(acc[nt], ah, bm0, bm1);
                    MMA_BF16(acc[nt], am, bh0, bh1);
                }
            }
        }
        if (!isQ) {
#pragma unroll
            for (int nt = 0; nt < 2; nt++) {
#pragma unroll
                for (int x = 0; x < 4; x++) {
                    int cc = colb + nt * 8 + 2 * lc + (x & 1);
                    int j  = mg * 16 + lr + ((x >> 1) << 3);
                    float v = acc[nt][x];
                    unsigned short h = bf16bits(v);
                    Uh16[cc * 72 + j] = h;
                    Um16[cc * 72 + j] = bf16bits(v - bf16f(h));
                }
            }
        }
        BARH();

        if (isQ) {
            const float* Ab = g_A + cbase * 4096;
#pragma unroll
            for (int j16 = 0; j16 < 4; j16++) {
                const float* ar0 = &Ab[(mg * 16 + lr) * 64 + j16 * 16 + 2 * lc];
                const float* ar1 = ar0 + 8 * 64;
                float2 p0 = *(const float2*)ar0;
                float2 p1 = *(const float2*)ar1;
                float2 p2 = *(const float2*)(ar0 + 8);
                float2 p3 = *(const float2*)(ar1 + 8);
                uint32_t ah[4], am[4];
                packsplit(p0.x, p0.y, ah[0], am[0]);
                packsplit(p1.x, p1.y, ah[1], am[1]);
                packsplit(p2.x, p2.y, ah[2], am[2]);
                packsplit(p3.x, p3.y, ah[3], am[3]);
#pragma unroll
                for (int nt = 0; nt < 2; nt++) {
                    int base = (colb + nt * 8 + lr) * UP + j16 * 8 + lc;
                    uint32_t bh0 = UhP[base], bh1 = UhP[base + 4];
                    uint32_t bm0 = UmP[base], bm1 = UmP[base + 4];
                    MMA_BF16(acc[nt], ah, bh0, bh1);
                    MMA_BF16(acc[nt], ah, bm0, bm1);
                    MMA_BF16(acc[nt], am, bh0, bh1);
                }
            }
            const size_t rr = row0 + mg * 16 + lr;
#pragma unroll
            for (int nt = 0; nt < 2; nt++) {
                int cc = cb0 + nt * 8 + 2 * lc;
                *(float2*)&g_O[rr * ND + cc]       = make_float2(acc[nt][0], acc[nt][1]);
                *(float2*)&g_O[(rr + 8) * ND + cc] = make_float2(acc[nt][2], acc[nt][3]);
            }
        }

        {
            const uint32_t* Kfh = g_Ktfh + cbase * 32768;
            const uint32_t* Kfm = g_Ktfm + cbase * 32768;
            const int ng0 = dn >> 3;
#pragma unroll
            for (int j16 = 0; j16 < 4; j16++) {
                int b0 = (colb + lr) * UP + j16 * 8 + lc;
                int b1 = (colb + lr + 8) * UP + j16 * 8 + lc;
                uint32_t ah[4] = {UhP[b0], UhP[b1], UhP[b0 + 4], UhP[b1 + 4]};
                uint32_t am[4] = {UmP[b0], UmP[b1], UmP[b0 + 4], UmP[b1 + 4]};
#pragma unroll
                for (int ng = 0; ng < 16; ng++) {
                    size_t fo = (size_t)((ng0 + ng) * 4 + j16) * 64 + lane * 2;
                    uint2 kh = *(const uint2*)&Kfh[fo];
                    uint2 km = *(const uint2*)&Kfm[fo];
                    MMA_BF16(Sreg[ng], ah, kh.x, kh.y);
                    MMA_BF16(Sreg[ng], ah, km.x, km.y);
                    MMA_BF16(Sreg[ng], am, kh.x, kh.y);
                }
            }
#pragma unroll
            for (int ng = 0; ng < 16; ng++) {
#pragma unroll
                for (int h8 = 0; h8 < 2; h8++) {
                    int cc = colb + lr + h8 * 8;
                    int widx = cc * SP + (dn >> 1) + ng * 4 + lc;
                    uint32_t hw, mw;
                    packsplit(Sreg[ng][h8 * 2], Sreg[ng][h8 * 2 + 1], hw, mw);
                    ShP[widx] = hw;
                    SmP[widx] = mw;
                }
            }
        }
        BARH();
    }
}

// =====================================================================
extern "C" void kernel_launch(void* const* d_in, const int* in_sizes, int n_in,
                              void* d_out, int out_size)
{
    int base = 1;
    if (n_in >= 10 && in_sizes[1] == 1) base = 2;
    const float* X    = (const float*)d_in[0];
    const float* Wq_w = (const float*)d_in[base + 0];
    const float* Wq_b = (const float*)d_in[base + 1];
    const float* Wk_w = (const float*)d_in[base + 2];
    const float* Wk_b = (const float*)d_in[base + 3];
    const float* Wv_w = (const float*)d_in[base + 4];
    const float* Wv_b = (const float*)d_in[base + 5];
    const float* Wo_w = (const float*)d_in[base + 6];
    const float* Wo_b = (const float*)d_in[base + 7];
    float* out = (float*)d_out;

    float *pQ, *pK, *pV, *pO;
    uint32_t *pXt, *pWq4, *pWk4, *pWv4, *pWo4;
    cudaGetSymbolAddress((void**)&pQ, g_Q);
    cudaGetSymbolAddress((void**)&pK, g_K);
    cudaGetSymbolAddress((void**)&pV, g_V);
    cudaGetSymbolAddress((void**)&pO, g_O);
    cudaGetSymbolAddress((void**)&pXt, g_Xt);
    cudaGetSymbolAddress((void**)&pWq4, g_Wq4);
    cudaGetSymbolAddress((void**)&pWk4, g_Wk4);
    cudaGetSymbolAddress((void**)&pWv4, g_Wv4);
    cudaGetSymbolAddress((void**)&pWo4, g_Wo4);

    const int nX4 = (int)((size_t)NROWS * ND / 4);
    const int nW4 = ND * ND / 4;

    conv_tf32<<<(nX4 + 255) / 256, 256>>>(X, pXt, nX4);
    conv_tf32<<<(nW4 + 255) / 256, 256>>>(Wq_w, pWq4, nW4);
    conv_tf32<<<(nW4 + 255) / 256, 256>>>(Wk_w, pWk4, nW4);
    conv_tf32<<<(nW4 + 255) / 256, 256>>>(Wv_w, pWv4, nW4);
    conv_tf32<<<(nW4 + 255) / 256, 256>>>(Wo_w, pWo4, nW4);

    cudaFuncSetAttribute(gemm_tf32, cudaFuncAttributeMaxDynamicSharedMemorySize, GSMEM);
    dim3 gg(ND / 128, NROWS / 128);
    gemm_tf32<<<gg, 256, GSMEM>>>(pXt, pWq4, Wq_b, pQ, NROWS, ND, ND);
    gemm_tf32<<<gg, 256, GSMEM>>>(pXt, pWk4, Wk_b, pK, NROWS, ND, ND);
    gemm_tf32<<<gg, 256, GSMEM>>>(pXt, pWv4, Wv_b, pV, NROWS, ND, ND);

    cudaFuncSetAttribute(prep_kernel, cudaFuncAttributeMaxDynamicSharedMemorySize, PREP_SMEM);
    prep_kernel<<<NB * 64, 256, PREP_SMEM>>>();
    cudaFuncSetAttribute(scan_tc, cudaFuncAttributeMaxDynamicSharedMemorySize, SCAN_SMEM3);
    scan_tc<<<dim3(32, NB), 512, SCAN_SMEM3>>>();

    // convert O to tf32 bits (reuse g_Xt), then O-projection
    conv_tf32<<<(nX4 + 255) / 256, 256>>>(pO, pXt, nX4);
    gemm_tf32<<<gg, 256, GSMEM>>>(pXt, pWo4, Wo_b, out, NROWS, ND, ND);
}